// round 1
// baseline (speedup 1.0000x reference)
#include <cuda_runtime.h>

#define NN 50000
#define DD 128
#define EE 600000

// ---- scratch (no allocations allowed; __device__ globals per rules) ----
__device__ float g_h[NN * DD];        // GEMM output / AGG input
__device__ float g_x[NN * DD];        // layer activations
__device__ int   g_deg[NN];
__device__ float g_dinv[NN];
__device__ int   g_rowstart[NN + 1];
__device__ int   g_cursor[NN];
__device__ int   g_esrc[EE];
__device__ int   g_oddor;
__device__ int   g_is64;

// ---------------------------------------------------------------- init
__global__ void k_init() {
    int i = blockIdx.x * blockDim.x + threadIdx.x;
    if (i < NN) g_deg[i] = 0;
    if (i == 0) g_oddor = 0;
}

// Detect edge_index dtype. View buffer as int32: indices [0, 2*EE) are within
// the buffer for BOTH int32 (exactly the whole buffer) and int64 (first half).
// If int64: odd words are high halves of values < 50000 -> all zero.
// If int32: odd words are real src/dst values -> some nonzero.
__global__ void k_detect(const int* __restrict__ ei32) {
    int i = blockIdx.x * blockDim.x + threadIdx.x;
    int v = 0;
    if (i < EE) v = ei32[2 * i + 1];
    if (__syncthreads_or(v)) {
        if (threadIdx.x == 0) atomicOr(&g_oddor, 1);
    }
}

__global__ void k_setflag() { g_is64 = (g_oddor == 0) ? 1 : 0; }

__device__ __forceinline__ int edge_at(const void* ei, int idx) {
    if (g_is64) return (int)((const long long*)ei)[idx];
    return ((const int*)ei)[idx];
}

// ---------------------------------------------------------------- degrees
__global__ void k_deg(const void* __restrict__ ei) {
    int e = blockIdx.x * blockDim.x + threadIdx.x;
    if (e < EE) {
        int d = edge_at(ei, EE + e);   // dst row
        atomicAdd(&g_deg[d], 1);
    }
}

__global__ void k_dinv() {
    int i = blockIdx.x * blockDim.x + threadIdx.x;
    if (i < NN) g_dinv[i] = rsqrtf((float)(g_deg[i] + 1));  // +1 self-loop
}

// Single-block exclusive scan of g_deg -> g_rowstart (+ cursor copy).
__global__ void k_scan() {
    __shared__ int sums[1024];
    const int CH = (NN + 1023) / 1024;  // 49
    int t = threadIdx.x;
    int base = t * CH;
    int s = 0;
    for (int i = 0; i < CH; i++) {
        int idx = base + i;
        if (idx < NN) s += g_deg[idx];
    }
    sums[t] = s;
    __syncthreads();
    for (int off = 1; off < 1024; off <<= 1) {
        int v = (t >= off) ? sums[t - off] : 0;
        __syncthreads();
        sums[t] += v;
        __syncthreads();
    }
    int run = (t == 0) ? 0 : sums[t - 1];
    for (int i = 0; i < CH; i++) {
        int idx = base + i;
        if (idx < NN) {
            g_rowstart[idx] = run;
            g_cursor[idx]   = run;
            run += g_deg[idx];
        }
    }
    if (t == 1023) g_rowstart[NN] = run;  // == EE
}

__global__ void k_csr(const void* __restrict__ ei) {
    int e = blockIdx.x * blockDim.x + threadIdx.x;
    if (e < EE) {
        int d = edge_at(ei, EE + e);
        int s = edge_at(ei, e);
        int p = atomicAdd(&g_cursor[d], 1);
        g_esrc[p] = s;
    }
}

// ---------------------------------------------------------------- GEMM
// H[N,128] = X[N,128] @ W[128,128]. Block: 64 rows x 128 cols, 256 threads,
// thread tile 4x8, K tiled by 32.
__global__ void __launch_bounds__(256) k_gemm(const float* __restrict__ X,
                                              const float* __restrict__ W,
                                              float* __restrict__ H) {
    __shared__ float XsT[32][64];     // [k][row] transposed for float4 reads
    __shared__ float Ws[32 * 128];    // [k][col]

    int tid = threadIdx.x;
    int rb  = blockIdx.x * 64;
    int rg  = tid >> 4;               // 0..15 -> rows rg*4..rg*4+3
    int cg  = tid & 15;               // 0..15 -> cols cg*8..cg*8+7

    float acc[4][8];
#pragma unroll
    for (int i = 0; i < 4; i++)
#pragma unroll
        for (int j = 0; j < 8; j++) acc[i][j] = 0.0f;

    for (int k0 = 0; k0 < 128; k0 += 32) {
        // W tile: 32x128 = 1024 float4, straight copy
        const float4* Wg = (const float4*)(W + k0 * 128);
        float4* Wsv = (float4*)Ws;
#pragma unroll
        for (int q = 0; q < 4; q++) Wsv[tid + q * 256] = Wg[tid + q * 256];

        // X tile: 64x32, stored transposed
#pragma unroll
        for (int q = 0; q < 2; q++) {
            int f  = tid * 2 + q;      // 0..511
            int r  = f >> 3;           // 0..63
            int c4 = f & 7;            // 0..7 (float4 within the 32-wide K tile)
            int row = rb + r;
            float4 v = make_float4(0.f, 0.f, 0.f, 0.f);
            if (row < NN) v = *(const float4*)(X + row * 128 + k0 + c4 * 4);
            XsT[c4 * 4 + 0][r] = v.x;
            XsT[c4 * 4 + 1][r] = v.y;
            XsT[c4 * 4 + 2][r] = v.z;
            XsT[c4 * 4 + 3][r] = v.w;
        }
        __syncthreads();

#pragma unroll
        for (int k = 0; k < 32; k++) {
            float4 xv = *(const float4*)&XsT[k][rg * 4];
            float4 w0 = *(const float4*)&Ws[k * 128 + cg * 8];
            float4 w1 = *(const float4*)&Ws[k * 128 + cg * 8 + 4];
            float xr[4] = {xv.x, xv.y, xv.z, xv.w};
            float wc[8] = {w0.x, w0.y, w0.z, w0.w, w1.x, w1.y, w1.z, w1.w};
#pragma unroll
            for (int j = 0; j < 8; j++) {
#pragma unroll
                for (int i = 0; i < 4; i++) acc[i][j] += xr[i] * wc[j];
            }
        }
        __syncthreads();
    }

#pragma unroll
    for (int i = 0; i < 4; i++) {
        int row = rb + rg * 4 + i;
        if (row < NN) {
            float4 o0 = make_float4(acc[i][0], acc[i][1], acc[i][2], acc[i][3]);
            float4 o1 = make_float4(acc[i][4], acc[i][5], acc[i][6], acc[i][7]);
            *(float4*)(H + row * 128 + cg * 8)     = o0;
            *(float4*)(H + row * 128 + cg * 8 + 4) = o1;
        }
    }
}

// ---------------------------------------------------------------- AGG
// Y[n] = sum_{e: dst=n} H[src]*dinv[src]*dinv[n] + H[n]*dinv[n]^2 + b, [relu]
// One warp per node; lane covers 4 cols (float4).
__global__ void __launch_bounds__(256) k_agg(const float* __restrict__ H,
                                             const float* __restrict__ bias,
                                             float* __restrict__ Y, int dorelu) {
    int warp = threadIdx.x >> 5;
    int lane = threadIdx.x & 31;
    int node = blockIdx.x * 8 + warp;
    if (node >= NN) return;

    const float4* Hv = (const float4*)H;
    float dn = g_dinv[node];
    float ws = dn * dn;
    float4 acc = Hv[node * 32 + lane];
    acc.x *= ws; acc.y *= ws; acc.z *= ws; acc.w *= ws;

    int e0 = g_rowstart[node];
    int e1 = g_rowstart[node + 1];
    for (int e = e0; e < e1; e++) {
        int s = g_esrc[e];
        float w = g_dinv[s] * dn;
        float4 hv = Hv[s * 32 + lane];
        acc.x += hv.x * w; acc.y += hv.y * w;
        acc.z += hv.z * w; acc.w += hv.w * w;
    }

    float4 bv = ((const float4*)bias)[lane];
    acc.x += bv.x; acc.y += bv.y; acc.z += bv.z; acc.w += bv.w;
    if (dorelu) {
        acc.x = fmaxf(acc.x, 0.f); acc.y = fmaxf(acc.y, 0.f);
        acc.z = fmaxf(acc.z, 0.f); acc.w = fmaxf(acc.w, 0.f);
    }
    ((float4*)Y)[node * 32 + lane] = acc;
}

__global__ void k_zerorow0(float* __restrict__ out) {
    out[threadIdx.x] = 0.0f;
}

// ---------------------------------------------------------------- launch
extern "C" void kernel_launch(void* const* d_in, const int* in_sizes, int n_in,
                              void* d_out, int out_size) {
    const float* emb = (const float*)d_in[0];
    const float* W1  = (const float*)d_in[1];
    const float* b1  = (const float*)d_in[2];
    const float* W2  = (const float*)d_in[3];
    const float* b2  = (const float*)d_in[4];
    const float* W3  = (const float*)d_in[5];
    const float* b3  = (const float*)d_in[6];
    const void*  ei  = d_in[7];
    float* out = (float*)d_out;

    float *hbuf = nullptr, *xbuf = nullptr;
    cudaGetSymbolAddress((void**)&hbuf, g_h);
    cudaGetSymbolAddress((void**)&xbuf, g_x);

    const int TB = 256;
    int gN = (NN + TB - 1) / TB;
    int gE = (EE + TB - 1) / TB;
    int gGemm = (NN + 63) / 64;     // 782
    int gAgg  = (NN + 7) / 8;       // 6250

    k_init<<<gN, TB>>>();
    k_detect<<<gE, TB>>>((const int*)ei);
    k_setflag<<<1, 1>>>();
    k_deg<<<gE, TB>>>(ei);
    k_dinv<<<gN, TB>>>();
    k_scan<<<1, 1024>>>();
    k_csr<<<gE, TB>>>(ei);

    // layer 1: x = relu(agg(emb @ W1) + b1)
    k_gemm<<<gGemm, TB>>>(emb, W1, hbuf);
    k_agg<<<gAgg, TB>>>(hbuf, b1, xbuf, 1);
    // layer 2
    k_gemm<<<gGemm, TB>>>(xbuf, W2, hbuf);
    k_agg<<<gAgg, TB>>>(hbuf, b2, xbuf, 1);
    // layer 3 (no relu), straight into d_out
    k_gemm<<<gGemm, TB>>>(xbuf, W3, hbuf);
    k_agg<<<gAgg, TB>>>(hbuf, b3, out, 0);

    k_zerorow0<<<1, 128>>>(out);
}

// round 7
// speedup vs baseline: 1.0621x; 1.0621x over previous
#include <cuda_runtime.h>
#include <cuda_bf16.h>
#include <mma.h>
#include <cstdint>

using namespace nvcuda;

#define NN 50000
#define DD 128
#define EE 600000

// ---- scratch (__device__ globals; no allocations allowed) ----
__device__ float         g_h[NN * DD];       // GEMM output / AGG input
__device__ __nv_bfloat16 g_xh[NN * DD];      // activation hi (bf16)
__device__ __nv_bfloat16 g_xl[NN * DD];      // activation lo (bf16)
__device__ __nv_bfloat16 g_wh[3 * DD * DD];  // W hi, [k][n] (as given)
__device__ __nv_bfloat16 g_wl[3 * DD * DD];  // W lo
__device__ int   g_deg[NN];
__device__ float g_dinv[NN];
__device__ int   g_rowstart[NN + 1];
__device__ int   g_cursor[NN];
__device__ int   g_esrc[EE];
__device__ int   g_oddor;
__device__ int   g_is64;

// ================= setup =================
__global__ void k_init() {
    int i = blockIdx.x * blockDim.x + threadIdx.x;
    if (i < NN) g_deg[i] = 0;
    if (i == 0) g_oddor = 0;
}
// Detect edge_index dtype (int64 per reference, but JAX w/o x64 gives int32).
// Viewing as int32: odd words are all zero iff int64 (values < 50000).
__global__ void k_detect(const int* __restrict__ ei32) {
    int i = blockIdx.x * blockDim.x + threadIdx.x;
    int v = 0;
    if (i < EE) v = ei32[2 * i + 1];
    if (__syncthreads_or(v)) {
        if (threadIdx.x == 0) atomicOr(&g_oddor, 1);
    }
}
__global__ void k_setflag() { g_is64 = (g_oddor == 0) ? 1 : 0; }

__device__ __forceinline__ int edge_at(const void* ei, int idx) {
    if (g_is64) return (int)((const long long*)ei)[idx];
    return ((const int*)ei)[idx];
}
__global__ void k_deg(const void* __restrict__ ei) {
    int e = blockIdx.x * blockDim.x + threadIdx.x;
    if (e < EE) atomicAdd(&g_deg[edge_at(ei, EE + e)], 1);
}
__global__ void k_dinv() {
    int i = blockIdx.x * blockDim.x + threadIdx.x;
    if (i < NN) g_dinv[i] = rsqrtf((float)(g_deg[i] + 1));  // +1 self-loop
}
__global__ void k_scan() {
    __shared__ int sums[1024];
    const int CH = (NN + 1023) / 1024;
    int t = threadIdx.x;
    int base = t * CH;
    int s = 0;
    for (int i = 0; i < CH; i++) { int idx = base + i; if (idx < NN) s += g_deg[idx]; }
    sums[t] = s;
    __syncthreads();
    for (int off = 1; off < 1024; off <<= 1) {
        int v = (t >= off) ? sums[t - off] : 0;
        __syncthreads();
        sums[t] += v;
        __syncthreads();
    }
    int run = (t == 0) ? 0 : sums[t - 1];
    for (int i = 0; i < CH; i++) {
        int idx = base + i;
        if (idx < NN) { g_rowstart[idx] = run; g_cursor[idx] = run; run += g_deg[idx]; }
    }
    if (t == 1023) g_rowstart[NN] = run;
}
__global__ void k_csr(const void* __restrict__ ei) {
    int e = blockIdx.x * blockDim.x + threadIdx.x;
    if (e < EE) {
        int d = edge_at(ei, EE + e);
        int s = edge_at(ei, e);
        g_esrc[atomicAdd(&g_cursor[d], 1)] = s;
    }
}

// ================= conversions =================
__device__ __forceinline__ void split_bf16(float v, __nv_bfloat16& h, __nv_bfloat16& l) {
    h = __float2bfloat16(v);
    l = __float2bfloat16(v - __bfloat162float(h));
}
// emb fp32 -> hi/lo bf16
__global__ void k_cvt_x(const float* __restrict__ X, __nv_bfloat16* __restrict__ xh,
                        __nv_bfloat16* __restrict__ xl) {
    int i = blockIdx.x * blockDim.x + threadIdx.x;  // over NN*32 float4
    if (i >= NN * 32) return;
    float4 v = ((const float4*)X)[i];
    __nv_bfloat16 h0, l0, h1, l1, h2, l2, h3, l3;
    split_bf16(v.x, h0, l0); split_bf16(v.y, h1, l1);
    split_bf16(v.z, h2, l2); split_bf16(v.w, h3, l3);
    __nv_bfloat162* H2 = (__nv_bfloat162*)xh;
    __nv_bfloat162* L2 = (__nv_bfloat162*)xl;
    H2[2 * i]     = __nv_bfloat162(h0, h1);
    H2[2 * i + 1] = __nv_bfloat162(h2, h3);
    L2[2 * i]     = __nv_bfloat162(l0, l1);
    L2[2 * i + 1] = __nv_bfloat162(l2, l3);
}
// W [k][n] fp32 -> hi/lo bf16, layout preserved (row_major B for WMMA)
__global__ void k_cvt_w(const float* __restrict__ W, __nv_bfloat16* __restrict__ wh,
                        __nv_bfloat16* __restrict__ wl) {
    int i = blockIdx.x * blockDim.x + threadIdx.x;  // 16384
    if (i >= DD * DD) return;
    __nv_bfloat16 h, l;
    split_bf16(W[i], h, l);
    wh[i] = h; wl[i] = l;
}

// ================= WMMA GEMM (HMMA — plain PTX, no sm_103a features) =================
// H[NN,128] = X @ W with X = Xh+Xl, W = Wh+Wl (bf16 split), fp32 accum.
// CTA tile M=128 x N=128 x K=128. 8 warps in 4(m) x 2(n) grid; warp tile 32x64.
__global__ void __launch_bounds__(256) k_gemm_wmma(const __nv_bfloat16* __restrict__ Xh,
                                                   const __nv_bfloat16* __restrict__ Xl,
                                                   const __nv_bfloat16* __restrict__ Wh,
                                                   const __nv_bfloat16* __restrict__ Wl,
                                                   float* __restrict__ H) {
    extern __shared__ __nv_bfloat16 sm[];
    __nv_bfloat16* Ah = sm;                  // 128x128 bf16 = 32 KB
    __nv_bfloat16* Al = Ah + DD * DD;
    __nv_bfloat16* Bh = Al + DD * DD;
    __nv_bfloat16* Bl = Bh + DD * DD;

    int tid = threadIdx.x;
    int rb = blockIdx.x * 128;

    // Stage tiles: 2048 uint4 per tile, 256 threads -> 8 iters each
#pragma unroll
    for (int t = 0; t < 8; t++) {
        int f = t * 256 + tid;       // 0..2047
        int row = f >> 4;            // 0..127
        int q = f & 15;              // uint4 (8 bf16) within row
        uint4 va = make_uint4(0, 0, 0, 0), vb = va;
        int gr = rb + row;
        if (gr < NN) {
            va = *(const uint4*)(Xh + (size_t)gr * DD + q * 8);
            vb = *(const uint4*)(Xl + (size_t)gr * DD + q * 8);
        }
        *(uint4*)(Ah + row * DD + q * 8) = va;
        *(uint4*)(Al + row * DD + q * 8) = vb;
        *(uint4*)(Bh + f * 8) = *(const uint4*)(Wh + f * 8);
        *(uint4*)(Bl + f * 8) = *(const uint4*)(Wl + f * 8);
    }
    __syncthreads();

    int warp = tid >> 5;
    int wm = warp >> 1;              // 0..3 -> rows wm*32
    int wn = warp & 1;               // 0..1 -> cols wn*64

    wmma::fragment<wmma::accumulator, 16, 16, 16, float> acc[2][4];
#pragma unroll
    for (int i = 0; i < 2; i++)
#pragma unroll
        for (int j = 0; j < 4; j++) wmma::fill_fragment(acc[i][j], 0.0f);

#pragma unroll
    for (int p = 0; p < 3; p++) {
        const __nv_bfloat16* A = (p == 2) ? Al : Ah;
        const __nv_bfloat16* B = (p == 1) ? Bl : Bh;
#pragma unroll
        for (int k = 0; k < DD; k += 16) {
            wmma::fragment<wmma::matrix_a, 16, 16, 16, __nv_bfloat16, wmma::row_major> af[2];
            wmma::fragment<wmma::matrix_b, 16, 16, 16, __nv_bfloat16, wmma::row_major> bf[4];
#pragma unroll
            for (int i = 0; i < 2; i++)
                wmma::load_matrix_sync(af[i], A + (wm * 32 + i * 16) * DD + k, DD);
#pragma unroll
            for (int j = 0; j < 4; j++)
                wmma::load_matrix_sync(bf[j], B + k * DD + wn * 64 + j * 16, DD);
#pragma unroll
            for (int i = 0; i < 2; i++)
#pragma unroll
                for (int j = 0; j < 4; j++)
                    wmma::mma_sync(acc[i][j], af[i], bf[j], acc[i][j]);
        }
    }

    if (rb + 128 <= NN) {
        // interior block: store fragments straight to global
#pragma unroll
        for (int i = 0; i < 2; i++)
#pragma unroll
            for (int j = 0; j < 4; j++)
                wmma::store_matrix_sync(H + (size_t)(rb + wm * 32 + i * 16) * DD + wn * 64 + j * 16,
                                        acc[i][j], DD, wmma::mem_row_major);
    } else {
        // boundary block: bounce through smem, guarded copy out
        __syncthreads();
        float* S = (float*)sm;       // 128x128 f32 = 64 KB (reuses Ah/Al)
#pragma unroll
        for (int i = 0; i < 2; i++)
#pragma unroll
            for (int j = 0; j < 4; j++)
                wmma::store_matrix_sync(S + (wm * 32 + i * 16) * DD + wn * 64 + j * 16,
                                        acc[i][j], DD, wmma::mem_row_major);
        __syncthreads();
#pragma unroll
        for (int t = 0; t < 16; t++) {
            int f = t * 256 + tid;   // 0..4095 float4s
            int row = f >> 5;
            int q = f & 31;
            int gr = rb + row;
            if (gr < NN)
                *(float4*)(H + (size_t)gr * DD + q * 4) = ((float4*)S)[f];
        }
    }
}

// ================= AGG =================
// Y[n] = sum_{e: dst=n} H[src]*dinv[src]*dinv[n] + H[n]*dinv[n]^2 + b, [relu]
// Output: fp32 (final layer) or bf16 hi/lo split (feeds next GEMM).
__global__ void __launch_bounds__(256) k_agg(const float* __restrict__ H,
                                             const float* __restrict__ bias,
                                             float* __restrict__ Yf,
                                             __nv_bfloat16* __restrict__ Yh,
                                             __nv_bfloat16* __restrict__ Yl,
                                             int dorelu) {
    int warp = threadIdx.x >> 5;
    int lane = threadIdx.x & 31;
    int node = blockIdx.x * 8 + warp;
    if (node >= NN) return;

    const float4* Hv = (const float4*)H;
    float dn = g_dinv[node];
    float ws = dn * dn;
    float4 acc = Hv[node * 32 + lane];
    acc.x *= ws; acc.y *= ws; acc.z *= ws; acc.w *= ws;

    int e0 = g_rowstart[node];
    int e1 = g_rowstart[node + 1];
    for (int e = e0; e < e1; e++) {
        int s = g_esrc[e];
        float w = g_dinv[s] * dn;
        float4 hv = Hv[s * 32 + lane];
        acc.x += hv.x * w; acc.y += hv.y * w;
        acc.z += hv.z * w; acc.w += hv.w * w;
    }

    float4 bv = ((const float4*)bias)[lane];
    acc.x += bv.x; acc.y += bv.y; acc.z += bv.z; acc.w += bv.w;
    if (dorelu) {
        acc.x = fmaxf(acc.x, 0.f); acc.y = fmaxf(acc.y, 0.f);
        acc.z = fmaxf(acc.z, 0.f); acc.w = fmaxf(acc.w, 0.f);
    }
    if (Yf) {
        ((float4*)Yf)[node * 32 + lane] = acc;
    } else {
        __nv_bfloat16 h0, l0, h1, l1, h2, l2, h3, l3;
        split_bf16(acc.x, h0, l0); split_bf16(acc.y, h1, l1);
        split_bf16(acc.z, h2, l2); split_bf16(acc.w, h3, l3);
        __nv_bfloat162* H2 = (__nv_bfloat162*)Yh;
        __nv_bfloat162* L2 = (__nv_bfloat162*)Yl;
        int idx = node * 64 + lane * 2;
        H2[idx]     = __nv_bfloat162(h0, h1);
        H2[idx + 1] = __nv_bfloat162(h2, h3);
        L2[idx]     = __nv_bfloat162(l0, l1);
        L2[idx + 1] = __nv_bfloat162(l2, l3);
    }
}

__global__ void k_zerorow0(float* __restrict__ out) { out[threadIdx.x] = 0.0f; }

// ================= launch =================
extern "C" void kernel_launch(void* const* d_in, const int* in_sizes, int n_in,
                              void* d_out, int out_size) {
    const float* emb = (const float*)d_in[0];
    const float* W1  = (const float*)d_in[1];
    const float* b1  = (const float*)d_in[2];
    const float* W2  = (const float*)d_in[3];
    const float* b2  = (const float*)d_in[4];
    const float* W3  = (const float*)d_in[5];
    const float* b3  = (const float*)d_in[6];
    const void*  ei  = d_in[7];
    float* out = (float*)d_out;

    float *hbuf = nullptr;
    __nv_bfloat16 *xh = nullptr, *xl = nullptr, *wh = nullptr, *wl = nullptr;
    cudaGetSymbolAddress((void**)&hbuf, g_h);
    cudaGetSymbolAddress((void**)&xh, g_xh);
    cudaGetSymbolAddress((void**)&xl, g_xl);
    cudaGetSymbolAddress((void**)&wh, g_wh);
    cudaGetSymbolAddress((void**)&wl, g_wl);

    const int SMEM_GEMM = 4 * DD * DD * 2;   // 128 KB dynamic
    cudaFuncSetAttribute(k_gemm_wmma, cudaFuncAttributeMaxDynamicSharedMemorySize, SMEM_GEMM);

    const int TB = 256;
    int gN = (NN + TB - 1) / TB;
    int gE = (EE + TB - 1) / TB;
    int gGemm = (NN + 127) / 128;            // 391
    int gAgg  = (NN + 7) / 8;                // 6250
    int gCvtX = (NN * 32 + TB - 1) / TB;
    int gCvtW = (DD * DD + TB - 1) / TB;

    // graph/topology setup
    k_init<<<gN, TB>>>();
    k_detect<<<gE, TB>>>((const int*)ei);
    k_setflag<<<1, 1>>>();
    k_deg<<<gE, TB>>>(ei);
    k_dinv<<<gN, TB>>>();
    k_scan<<<1, 1024>>>();
    k_csr<<<gE, TB>>>(ei);

    // precision-split conversions
    k_cvt_x<<<gCvtX, TB>>>(emb, xh, xl);
    k_cvt_w<<<gCvtW, TB>>>(W1, wh + 0 * DD * DD, wl + 0 * DD * DD);
    k_cvt_w<<<gCvtW, TB>>>(W2, wh + 1 * DD * DD, wl + 1 * DD * DD);
    k_cvt_w<<<gCvtW, TB>>>(W3, wh + 2 * DD * DD, wl + 2 * DD * DD);

    // layer 1
    k_gemm_wmma<<<gGemm, TB, SMEM_GEMM>>>(xh, xl, wh + 0 * DD * DD, wl + 0 * DD * DD, hbuf);
    k_agg<<<gAgg, TB>>>(hbuf, b1, nullptr, xh, xl, 1);
    // layer 2
    k_gemm_wmma<<<gGemm, TB, SMEM_GEMM>>>(xh, xl, wh + 1 * DD * DD, wl + 1 * DD * DD, hbuf);
    k_agg<<<gAgg, TB>>>(hbuf, b2, nullptr, xh, xl, 1);
    // layer 3 -> d_out (fp32, no relu)
    k_gemm_wmma<<<gGemm, TB, SMEM_GEMM>>>(xh, xl, wh + 2 * DD * DD, wl + 2 * DD * DD, hbuf);
    k_agg<<<gAgg, TB>>>(hbuf, b3, out, nullptr, nullptr, 0);

    k_zerorow0<<<1, 128>>>(out);
}

// round 11
// speedup vs baseline: 1.2902x; 1.2148x over previous
#include <cuda_runtime.h>
#include <cuda_bf16.h>
#include <mma.h>
#include <cstdint>

using namespace nvcuda;

#define NN 50000
#define DD 128
#define EE 600000

// ---- scratch (__device__ globals; no allocations allowed) ----
__device__ float         g_h[NN * DD];       // GEMM output / AGG input
__device__ __nv_bfloat16 g_xh[NN * DD];      // activation hi (bf16)
__device__ __nv_bfloat16 g_xl[NN * DD];      // activation lo (bf16)
__device__ __nv_bfloat16 g_wh[3 * DD * DD];  // W hi, [k][n] (as given)
__device__ __nv_bfloat16 g_wl[3 * DD * DD];  // W lo
__device__ int   g_deg[NN];
__device__ float g_dinv[NN];
__device__ int   g_rowstart[NN];
__device__ int   g_cursor[NN];
__device__ int2  g_epack[EE];                // {src, bits(dinv[src])}
__device__ int   g_total;
__device__ int   g_oddor;
__device__ int   g_is64;

// ================= setup =================
__global__ void k_init() {
    int i = blockIdx.x * blockDim.x + threadIdx.x;
    if (i < NN) g_deg[i] = 0;
    if (i == 0) { g_oddor = 0; g_total = 0; }
}
// Detect edge_index dtype (int64 per reference, but JAX w/o x64 gives int32).
// Viewing as int32: odd words are all zero iff int64 (values < 50000).
__global__ void k_detect(const int* __restrict__ ei32) {
    int i = blockIdx.x * blockDim.x + threadIdx.x;
    int v = 0;
    if (i < EE) v = ei32[2 * i + 1];
    if (__syncthreads_or(v)) {
        if (threadIdx.x == 0) atomicOr(&g_oddor, 1);
    }
}
__global__ void k_setflag() { g_is64 = (g_oddor == 0) ? 1 : 0; }

__device__ __forceinline__ int edge_at(const void* ei, int idx) {
    if (g_is64) return (int)((const long long*)ei)[idx];
    return ((const int*)ei)[idx];
}
__global__ void k_deg(const void* __restrict__ ei) {
    int e = blockIdx.x * blockDim.x + threadIdx.x;
    if (e < EE) atomicAdd(&g_deg[edge_at(ei, EE + e)], 1);
}
// dinv + CSR segment offsets (order-free: contiguity is all AGG needs)
__global__ void k_dinv_off() {
    int i = blockIdx.x * blockDim.x + threadIdx.x;
    if (i < NN) {
        int d = g_deg[i];
        g_dinv[i] = rsqrtf((float)(d + 1));  // +1 self-loop
        int st = atomicAdd(&g_total, d);
        g_rowstart[i] = st;
        g_cursor[i]   = st;
    }
}
__global__ void k_csr(const void* __restrict__ ei) {
    int e = blockIdx.x * blockDim.x + threadIdx.x;
    if (e < EE) {
        int d = edge_at(ei, EE + e);
        int s = edge_at(ei, e);
        int p = atomicAdd(&g_cursor[d], 1);
        g_epack[p] = make_int2(s, __float_as_int(g_dinv[s]));
    }
}

// ================= conversions =================
__device__ __forceinline__ void split_bf16(float v, __nv_bfloat16& h, __nv_bfloat16& l) {
    h = __float2bfloat16(v);
    l = __float2bfloat16(v - __bfloat162float(h));
}
__global__ void k_cvt_x(const float* __restrict__ X, __nv_bfloat16* __restrict__ xh,
                        __nv_bfloat16* __restrict__ xl) {
    int i = blockIdx.x * blockDim.x + threadIdx.x;  // over NN*32 float4
    if (i >= NN * 32) return;
    float4 v = ((const float4*)X)[i];
    __nv_bfloat16 h0, l0, h1, l1, h2, l2, h3, l3;
    split_bf16(v.x, h0, l0); split_bf16(v.y, h1, l1);
    split_bf16(v.z, h2, l2); split_bf16(v.w, h3, l3);
    __nv_bfloat162* H2 = (__nv_bfloat162*)xh;
    __nv_bfloat162* L2 = (__nv_bfloat162*)xl;
    H2[2 * i]     = __nv_bfloat162(h0, h1);
    H2[2 * i + 1] = __nv_bfloat162(h2, h3);
    L2[2 * i]     = __nv_bfloat162(l0, l1);
    L2[2 * i + 1] = __nv_bfloat162(l2, l3);
}
__global__ void k_cvt_w(const float* __restrict__ W, __nv_bfloat16* __restrict__ wh,
                        __nv_bfloat16* __restrict__ wl) {
    int i = blockIdx.x * blockDim.x + threadIdx.x;  // 16384
    if (i >= DD * DD) return;
    __nv_bfloat16 h, l;
    split_bf16(W[i], h, l);
    wh[i] = h; wl[i] = l;
}

// ================= WMMA GEMM (HMMA) =================
// H[NN,128] = X @ W with X = Xh+Xl, W = Wh+Wl (bf16 split), fp32 accum.
// CTA tile M=128 x N=128 x K=128. 8 warps in 4(m) x 2(n); warp tile 32x64.
__global__ void __launch_bounds__(256) k_gemm_wmma(const __nv_bfloat16* __restrict__ Xh,
                                                   const __nv_bfloat16* __restrict__ Xl,
                                                   const __nv_bfloat16* __restrict__ Wh,
                                                   const __nv_bfloat16* __restrict__ Wl,
                                                   float* __restrict__ H) {
    extern __shared__ __nv_bfloat16 sm[];
    __nv_bfloat16* Ah = sm;                  // 128x128 bf16 = 32 KB each
    __nv_bfloat16* Al = Ah + DD * DD;
    __nv_bfloat16* Bh = Al + DD * DD;
    __nv_bfloat16* Bl = Bh + DD * DD;

    int tid = threadIdx.x;
    int rb = blockIdx.x * 128;

#pragma unroll
    for (int t = 0; t < 8; t++) {
        int f = t * 256 + tid;       // 0..2047 uint4s
        int row = f >> 4;
        int q = f & 15;
        uint4 va = make_uint4(0, 0, 0, 0), vb = va;
        int gr = rb + row;
        if (gr < NN) {
            va = *(const uint4*)(Xh + (size_t)gr * DD + q * 8);
            vb = *(const uint4*)(Xl + (size_t)gr * DD + q * 8);
        }
        *(uint4*)(Ah + row * DD + q * 8) = va;
        *(uint4*)(Al + row * DD + q * 8) = vb;
        *(uint4*)(Bh + f * 8) = *(const uint4*)(Wh + f * 8);
        *(uint4*)(Bl + f * 8) = *(const uint4*)(Wl + f * 8);
    }
    __syncthreads();

    int warp = tid >> 5;
    int wm = warp >> 1;
    int wn = warp & 1;

    wmma::fragment<wmma::accumulator, 16, 16, 16, float> acc[2][4];
#pragma unroll
    for (int i = 0; i < 2; i++)
#pragma unroll
        for (int j = 0; j < 4; j++) wmma::fill_fragment(acc[i][j], 0.0f);

#pragma unroll
    for (int p = 0; p < 3; p++) {
        const __nv_bfloat16* A = (p == 2) ? Al : Ah;
        const __nv_bfloat16* B = (p == 1) ? Bl : Bh;
#pragma unroll
        for (int k = 0; k < DD; k += 16) {
            wmma::fragment<wmma::matrix_a, 16, 16, 16, __nv_bfloat16, wmma::row_major> af[2];
            wmma::fragment<wmma::matrix_b, 16, 16, 16, __nv_bfloat16, wmma::row_major> bf[4];
#pragma unroll
            for (int i = 0; i < 2; i++)
                wmma::load_matrix_sync(af[i], A + (wm * 32 + i * 16) * DD + k, DD);
#pragma unroll
            for (int j = 0; j < 4; j++)
                wmma::load_matrix_sync(bf[j], B + k * DD + wn * 64 + j * 16, DD);
#pragma unroll
            for (int i = 0; i < 2; i++)
#pragma unroll
                for (int j = 0; j < 4; j++)
                    wmma::mma_sync(acc[i][j], af[i], bf[j], acc[i][j]);
        }
    }

    if (rb + 128 <= NN) {
#pragma unroll
        for (int i = 0; i < 2; i++)
#pragma unroll
            for (int j = 0; j < 4; j++)
                wmma::store_matrix_sync(H + (size_t)(rb + wm * 32 + i * 16) * DD + wn * 64 + j * 16,
                                        acc[i][j], DD, wmma::mem_row_major);
    } else {
        __syncthreads();
        float* S = (float*)sm;
#pragma unroll
        for (int i = 0; i < 2; i++)
#pragma unroll
            for (int j = 0; j < 4; j++)
                wmma::store_matrix_sync(S + (wm * 32 + i * 16) * DD + wn * 64 + j * 16,
                                        acc[i][j], DD, wmma::mem_row_major);
        __syncthreads();
#pragma unroll
        for (int t = 0; t < 16; t++) {
            int f = t * 256 + tid;
            int row = f >> 5;
            int q = f & 31;
            int gr = rb + row;
            if (gr < NN)
                *(float4*)(H + (size_t)gr * DD + q * 4) = ((float4*)S)[f];
        }
    }
}

// ================= AGG =================
// y[n] = dn^2*H[n] + dn * sum_e w_s*H[s] + b, [relu]; w_s = dinv[src] packed per edge.
// One warp per node, edge loop unrolled x4 for MLP.
__global__ void __launch_bounds__(256) k_agg(const float* __restrict__ H,
                                             const float* __restrict__ bias,
                                             float* __restrict__ Yf,
                                             __nv_bfloat16* __restrict__ Yh,
                                             __nv_bfloat16* __restrict__ Yl,
                                             int dorelu) {
    int warp = threadIdx.x >> 5;
    int lane = threadIdx.x & 31;
    int node = blockIdx.x * 8 + warp;
    if (node >= NN) return;

    const float4* __restrict__ Hv = (const float4*)H;
    const int2* __restrict__ EP = g_epack;

    float dn = g_dinv[node];
    int e0 = g_rowstart[node];
    int deg = g_deg[node];
    int e1 = e0 + deg;

    float4 self = Hv[node * 32 + lane];
    float4 acc = make_float4(0.f, 0.f, 0.f, 0.f);

    int e = e0;
#pragma unroll 1
    for (; e + 4 <= e1; e += 4) {
        int2 p0 = EP[e], p1 = EP[e + 1], p2 = EP[e + 2], p3 = EP[e + 3];
        float4 h0 = Hv[p0.x * 32 + lane];
        float4 h1 = Hv[p1.x * 32 + lane];
        float4 h2 = Hv[p2.x * 32 + lane];
        float4 h3 = Hv[p3.x * 32 + lane];
        float w0 = __int_as_float(p0.y), w1 = __int_as_float(p1.y);
        float w2 = __int_as_float(p2.y), w3 = __int_as_float(p3.y);
        acc.x += h0.x * w0 + h1.x * w1 + h2.x * w2 + h3.x * w3;
        acc.y += h0.y * w0 + h1.y * w1 + h2.y * w2 + h3.y * w3;
        acc.z += h0.z * w0 + h1.z * w1 + h2.z * w2 + h3.z * w3;
        acc.w += h0.w * w0 + h1.w * w1 + h2.w * w2 + h3.w * w3;
    }
#pragma unroll 1
    for (; e < e1; e++) {
        int2 p = EP[e];
        float w = __int_as_float(p.y);
        float4 hv = Hv[p.x * 32 + lane];
        acc.x += hv.x * w; acc.y += hv.y * w;
        acc.z += hv.z * w; acc.w += hv.w * w;
    }

    float ws = dn * dn;
    float4 bv = ((const float4*)bias)[lane];
    float4 r;
    r.x = self.x * ws + acc.x * dn + bv.x;
    r.y = self.y * ws + acc.y * dn + bv.y;
    r.z = self.z * ws + acc.z * dn + bv.z;
    r.w = self.w * ws + acc.w * dn + bv.w;
    if (dorelu) {
        r.x = fmaxf(r.x, 0.f); r.y = fmaxf(r.y, 0.f);
        r.z = fmaxf(r.z, 0.f); r.w = fmaxf(r.w, 0.f);
    }
    if (Yf) {
        ((float4*)Yf)[node * 32 + lane] = r;
    } else {
        __nv_bfloat16 h0, l0, h1, l1, h2, l2, h3, l3;
        split_bf16(r.x, h0, l0); split_bf16(r.y, h1, l1);
        split_bf16(r.z, h2, l2); split_bf16(r.w, h3, l3);
        __nv_bfloat162* H2 = (__nv_bfloat162*)Yh;
        __nv_bfloat162* L2 = (__nv_bfloat162*)Yl;
        int idx = node * 64 + lane * 2;
        H2[idx]     = __nv_bfloat162(h0, h1);
        H2[idx + 1] = __nv_bfloat162(h2, h3);
        L2[idx]     = __nv_bfloat162(l0, l1);
        L2[idx + 1] = __nv_bfloat162(l2, l3);
    }
}

__global__ void k_zerorow0(float* __restrict__ out) { out[threadIdx.x] = 0.0f; }

// ================= launch =================
extern "C" void kernel_launch(void* const* d_in, const int* in_sizes, int n_in,
                              void* d_out, int out_size) {
    const float* emb = (const float*)d_in[0];
    const float* W1  = (const float*)d_in[1];
    const float* b1  = (const float*)d_in[2];
    const float* W2  = (const float*)d_in[3];
    const float* b2  = (const float*)d_in[4];
    const float* W3  = (const float*)d_in[5];
    const float* b3  = (const float*)d_in[6];
    const void*  ei  = d_in[7];
    float* out = (float*)d_out;

    float *hbuf = nullptr;
    __nv_bfloat16 *xh = nullptr, *xl = nullptr, *wh = nullptr, *wl = nullptr;
    cudaGetSymbolAddress((void**)&hbuf, g_h);
    cudaGetSymbolAddress((void**)&xh, g_xh);
    cudaGetSymbolAddress((void**)&xl, g_xl);
    cudaGetSymbolAddress((void**)&wh, g_wh);
    cudaGetSymbolAddress((void**)&wl, g_wl);

    const int SMEM_GEMM = 4 * DD * DD * 2;   // 128 KB dynamic
    cudaFuncSetAttribute(k_gemm_wmma, cudaFuncAttributeMaxDynamicSharedMemorySize, SMEM_GEMM);

    const int TB = 256;
    int gN = (NN + TB - 1) / TB;
    int gE = (EE + TB - 1) / TB;
    int gGemm = (NN + 127) / 128;            // 391
    int gAgg  = (NN + 7) / 8;                // 6250
    int gCvtX = (NN * 32 + TB - 1) / TB;
    int gCvtW = (DD * DD + TB - 1) / TB;

    // graph/topology setup
    k_init<<<gN, TB>>>();
    k_detect<<<gE, TB>>>((const int*)ei);
    k_setflag<<<1, 1>>>();
    k_deg<<<gE, TB>>>(ei);
    k_dinv_off<<<gN, TB>>>();
    k_csr<<<gE, TB>>>(ei);

    // precision-split conversions
    k_cvt_x<<<gCvtX, TB>>>(emb, xh, xl);
    k_cvt_w<<<gCvtW, TB>>>(W1, wh + 0 * DD * DD, wl + 0 * DD * DD);
    k_cvt_w<<<gCvtW, TB>>>(W2, wh + 1 * DD * DD, wl + 1 * DD * DD);
    k_cvt_w<<<gCvtW, TB>>>(W3, wh + 2 * DD * DD, wl + 2 * DD * DD);

    // layer 1
    k_gemm_wmma<<<gGemm, TB, SMEM_GEMM>>>(xh, xl, wh + 0 * DD * DD, wl + 0 * DD * DD, hbuf);
    k_agg<<<gAgg, TB>>>(hbuf, b1, nullptr, xh, xl, 1);
    // layer 2
    k_gemm_wmma<<<gGemm, TB, SMEM_GEMM>>>(xh, xl, wh + 1 * DD * DD, wl + 1 * DD * DD, hbuf);
    k_agg<<<gAgg, TB>>>(hbuf, b2, nullptr, xh, xl, 1);
    // layer 3 -> d_out (fp32, no relu)
    k_gemm_wmma<<<gGemm, TB, SMEM_GEMM>>>(xh, xl, wh + 2 * DD * DD, wl + 2 * DD * DD, hbuf);
    k_agg<<<gAgg, TB>>>(hbuf, b3, out, nullptr, nullptr, 0);

    k_zerorow0<<<1, 128>>>(out);
}